// round 7
// baseline (speedup 1.0000x reference)
#include <cuda_runtime.h>
#include <stdint.h>

// FP32 "pulse bits" (B,32 floats of 0.0/1.0, MSB-first) -> FP64 "pulse bits" (B,64).
// fp64: exp11 = 0 (e==0), 2047 (e==255), else e+896; mant52 = m<<29, NaN -> 1<<51, Inf -> 0.
//
// One WARP per R rows, software-pipelined:
//   Phase 1: R back-to-back coalesced LDG.32 (lane l <- float l of each row)
//            -> R*128B in flight per warp to cover ~577cyc DRAM latency.
//   Phase 2: per row: 1 VOTE (ballot pack) + ~14 ALU decode + 1 coalesced STG.64.
// R6: R=8 -> 120.4us @ DRAM 81.6%. R7: R=16 to raise avg bytes-in-flight.

#define R 16
#define THREADS 256

__global__ void __launch_bounds__(THREADS)
fp32bits_to_fp64bits_kernel(const unsigned* __restrict__ in,
                            uint2* __restrict__ out,
                            int nrows)
{
    const int lane   = threadIdx.x & 31;
    const int warpId = (int)((blockIdx.x * blockDim.x + threadIdx.x) >> 5);
    const size_t row0 = (size_t)warpId * R;
    if (row0 >= (size_t)nrows) return;

    const unsigned ONE  = 0x3F800000u;            // bits of 1.0f
    const int      sh_y = 30 - 2 * (lane & 15);   // low bit of this lane's 2-bit field
    const bool     useHi = lane < 16;

    const unsigned* p = in + row0 * 32 + lane;
    uint2* q = out + row0 * 32 + lane;

    if (row0 + R <= (size_t)nrows) {
        // ---- Phase 1: batch all loads (maximize bytes in flight) ----
        unsigned v[R];
        #pragma unroll
        for (int r = 0; r < R; r++) v[r] = __ldcs(p + r * 32);

        // ---- Phase 2: pack, decode, store ----
        #pragma unroll
        for (int r = 0; r < R; r++) {
            unsigned u = __brev(__ballot_sync(0xFFFFFFFFu, v[r] != 0u));

            unsigned e = (u >> 23) & 0xFFu;
            unsigned m = u & 0x7FFFFFu;

            unsigned exp11  = (e == 0u) ? 0u : (e + 896u);
            unsigned mant23 = m;
            if (e == 255u) {                       // Inf / NaN
                exp11  = 2047u;
                mant23 = m ? (1u << 22) : 0u;      // NaN -> quiet bit only
            }

            unsigned hi = (u & 0x80000000u) | (exp11 << 20) | (mant23 >> 3);
            unsigned lo = mant23 << 29;            // only bits 31..29 may be set

            unsigned src = useHi ? hi : lo;
            unsigned two = (src >> sh_y) & 3u;     // this lane's 2 output bits
            uint2 o;
            o.x = (two & 2u) ? ONE : 0u;
            o.y = (two & 1u) ? ONE : 0u;
            __stcs(q + r * 32, o);
        }
    } else {
        // Tail (not hit for B = 2^21, kept for safety)
        for (int r = 0; r < R && row0 + r < (size_t)nrows; r++) {
            unsigned v = __ldcs(p + r * 32);
            unsigned u = __brev(__ballot_sync(0xFFFFFFFFu, v != 0u));
            unsigned e = (u >> 23) & 0xFFu;
            unsigned m = u & 0x7FFFFFu;
            unsigned exp11  = (e == 0u) ? 0u : (e + 896u);
            unsigned mant23 = m;
            if (e == 255u) { exp11 = 2047u; mant23 = m ? (1u << 22) : 0u; }
            unsigned hi = (u & 0x80000000u) | (exp11 << 20) | (mant23 >> 3);
            unsigned lo = mant23 << 29;
            unsigned src = useHi ? hi : lo;
            unsigned two = (src >> sh_y) & 3u;
            uint2 o;
            o.x = (two & 2u) ? ONE : 0u;
            o.y = (two & 1u) ? ONE : 0u;
            __stcs(q + r * 32, o);
        }
    }
}

extern "C" void kernel_launch(void* const* d_in, const int* in_sizes, int n_in,
                              void* d_out, int out_size)
{
    const unsigned* in  = (const unsigned*)d_in[0];
    uint2*          out = (uint2*)d_out;
    const int nrows = in_sizes[0] / 32;

    const int warps  = (nrows + R - 1) / R;
    const int blocks = (warps + (THREADS / 32) - 1) / (THREADS / 32);
    fp32bits_to_fp64bits_kernel<<<blocks, THREADS>>>(in, out, nrows);
}

// round 10
// speedup vs baseline: 1.0279x; 1.0279x over previous
#include <cuda_runtime.h>
#include <stdint.h>

// FP32 "pulse bits" (B,32 floats of 0.0/1.0, MSB-first) -> FP64 "pulse bits" (B,64).
// fp64: exp11 = 0 (e==0), 2047 (e==255), else e+896; mant52 = m<<29, NaN -> 1<<51, Inf -> 0.
//
// One WARP per R rows, software-pipelined:
//   Phase 1: R back-to-back coalesced LDG.32 (lane l <- float l of each row).
//   Phase 2: rows processed in PAIRS: 2 VOTEs, each half-warp selects its row's
//            packed word, decodes once, and stores 4 output words via one STG.128
//            (lanes 0-15 -> row r, lanes 16-31 -> row r+1; 512B contiguous/warp).
// History: R5 interleaved 180us @53% DRAM; R6 R=8 batched 120.4us @81.6%;
//          R7 R=16 neutral (122.6us) -> at/near mixed-stream HBM ceiling.

#define R 8
#define THREADS 256

__global__ void __launch_bounds__(THREADS)
fp32bits_to_fp64bits_kernel(const unsigned* __restrict__ in,
                            uint4* __restrict__ out,   // out as uint4 (4 floats)
                            int nrows)
{
    const int lane   = threadIdx.x & 31;
    const int warpId = (int)((blockIdx.x * blockDim.x + threadIdx.x) >> 5);
    const size_t row0 = (size_t)warpId * R;
    if (row0 >= (size_t)nrows) return;

    const unsigned ONE = 0x3F800000u;          // bits of 1.0f
    const int  ll      = lane & 15;            // uint4 slot within this lane's row
    const bool lowHalf = lane < 16;            // lanes 0-15 -> even row of pair
    const int  nshift  = 28 - 4 * (ll & 7);    // nibble position in hi/lo word
    const bool useHi   = ll < 8;               // slots 0-7 from hi word, 8-15 from lo

    const unsigned* p = in + row0 * 32 + lane;
    // uint4 index for this lane's store: rowbase*16 + lane  (row = rowbase + (lane>>4))
    uint4* q = out + row0 * 16 + lane;

    if (row0 + R <= (size_t)nrows) {
        // ---- Phase 1: batch all loads (bytes in flight covers DRAM latency) ----
        unsigned v[R];
        #pragma unroll
        for (int r = 0; r < R; r++) v[r] = __ldcs(p + r * 32);

        // ---- Phase 2: decode + store, two rows per iteration ----
        #pragma unroll
        for (int r = 0; r < R; r += 2) {
            unsigned be = __ballot_sync(0xFFFFFFFFu, v[r]     != 0u);
            unsigned bo = __ballot_sync(0xFFFFFFFFu, v[r + 1] != 0u);
            unsigned u  = __brev(lowHalf ? be : bo);   // this half-warp's row word

            unsigned e = (u >> 23) & 0xFFu;
            unsigned m = u & 0x7FFFFFu;

            unsigned exp11  = (e == 0u) ? 0u : (e + 896u);
            unsigned mant23 = m;
            if (e == 255u) {                           // Inf / NaN
                exp11  = 2047u;
                mant23 = m ? (1u << 22) : 0u;          // NaN -> quiet bit only
            }

            unsigned hi = (u & 0x80000000u) | (exp11 << 20) | (mant23 >> 3);
            unsigned lo = mant23 << 29;                // only bits 31..29 may be set

            unsigned src = useHi ? hi : lo;
            unsigned nib = (src >> nshift) & 0xFu;     // this lane's 4 output bits
            uint4 o;
            o.x = (nib & 8u) ? ONE : 0u;
            o.y = (nib & 4u) ? ONE : 0u;
            o.z = (nib & 2u) ? ONE : 0u;
            o.w = (nib & 1u) ? ONE : 0u;
            __stcs(q + r * 16, o);                     // rows r (lanes 0-15) / r+1 (16-31)
        }
    } else {
        // Tail (not hit for B = 2^21): scalar-safe path, one row at a time.
        for (int r = 0; r < R && row0 + r < (size_t)nrows; r++) {
            unsigned v = __ldcs(p + r * 32);
            unsigned u = __brev(__ballot_sync(0xFFFFFFFFu, v != 0u));
            unsigned e = (u >> 23) & 0xFFu;
            unsigned m = u & 0x7FFFFFu;
            unsigned exp11  = (e == 0u) ? 0u : (e + 896u);
            unsigned mant23 = m;
            if (e == 255u) { exp11 = 2047u; mant23 = m ? (1u << 22) : 0u; }
            unsigned hi = (u & 0x80000000u) | (exp11 << 20) | (mant23 >> 3);
            unsigned lo = mant23 << 29;
            // lane stores 2 words via the uint2 view of this row
            unsigned src = (lane < 16) ? hi : lo;
            unsigned two = (src >> (30 - 2 * (lane & 15))) & 3u;
            uint2 o2;
            o2.x = (two & 2u) ? ONE : 0u;
            o2.y = (two & 1u) ? ONE : 0u;
            uint2* qt = (uint2*)(out + (row0 + r) * 16) + lane;
            __stcs(qt, o2);
        }
    }
}

extern "C" void kernel_launch(void* const* d_in, const int* in_sizes, int n_in,
                              void* d_out, int out_size)
{
    const unsigned* in  = (const unsigned*)d_in[0];
    uint4*          out = (uint4*)d_out;
    const int nrows = in_sizes[0] / 32;

    const int warps  = (nrows + R - 1) / R;
    const int blocks = (warps + (THREADS / 32) - 1) / (THREADS / 32);
    fp32bits_to_fp64bits_kernel<<<blocks, THREADS>>>(in, out, nrows);
}